// round 3
// baseline (speedup 1.0000x reference)
#include <cuda_runtime.h>

#define C_DIM 2048
#define B_DIM 64
#define I_DIM 8
#define U_DIM 32
#define D_DIM 16
#define UD    512
#define NBLK  148     // k_accum grid

typedef unsigned long long u64;

// ---- scratch (static __device__: allocation-free) ----
__device__ float g_xt[C_DIM * B_DIM * I_DIM];     // x transposed: [c][b][i]
__device__ float g_spart[NBLK * B_DIM * UD];      // per-block s partials
__device__ float g_v[B_DIM * UD];                 // squashed v
__device__ float g_b[C_DIM * U_DIM];              // routing logits
__device__ float g_cij[C_DIM * U_DIM];            // softmax coupling coeffs

__device__ __forceinline__ u64 mul2(u64 a, u64 b) {
    u64 r; asm("mul.rn.f32x2 %0, %1, %2;" : "=l"(r) : "l"(a), "l"(b)); return r;
}
__device__ __forceinline__ u64 fma2(u64 a, u64 b, u64 c) {
    u64 r; asm("fma.rn.f32x2 %0, %1, %2, %3;" : "=l"(r) : "l"(a), "l"(b), "l"(c)); return r;
}
__device__ __forceinline__ float hadd2(u64 a) {
    float lo, hi; asm("mov.b64 {%0,%1}, %2;" : "=f"(lo), "=f"(hi) : "l"(a));
    return lo + hi;
}
// volatile loads: pin in place; stop ptxas hoisting loop-invariant loads into
// 32 live registers (spill bomb at 64-reg budget)
__device__ __forceinline__ float ldg_f(const float* p) {
    float r; asm volatile("ld.global.nc.f32 %0, [%1];" : "=f"(r) : "l"(p)); return r;
}
__device__ __forceinline__ void ldg_2u64(const float* p, u64& a, u64& b) {
    asm volatile("ld.global.nc.v2.u64 {%0,%1}, [%2];" : "=l"(a), "=l"(b) : "l"(p));
}

// x (B,I,C) -> g_xt[c][b][i]
__global__ void k_transpose(const float* __restrict__ x) {
    int idx = blockIdx.x * blockDim.x + threadIdx.x;
    if (idx >= C_DIM * B_DIM * I_DIM) return;
    int c = idx >> 9;
    int r = idx & 511;
    int b = r >> 3;
    int i = r & 7;
    g_xt[idx] = x[(b * I_DIM + i) * C_DIM + c];
}

// ---------------------------------------------------------------------------
// k_accum: s[b,ud] += cij[c,u] * u_hat[b,c,ud], barrier-free, s in registers.
// 1024 threads = 32 warps: wu = w&3 (ud column of 128), wb = w>>2 (8 batches).
// Lane owns ud = wu*128 + k*32 + lane, k = 0..3; batches b = wb*8 + r, r = 0..7.
// UNI=1: cij = 1/32 (first iteration).
// ---------------------------------------------------------------------------
template <int UNI>
__global__ void __launch_bounds__(1024, 1) k_accum(const float* __restrict__ W) {
    const int tid  = threadIdx.x;
    const int w    = tid >> 5;
    const int lane = tid & 31;
    const int wu   = w & 3;
    const int wb   = w >> 2;

    float sacc[4][8];
#pragma unroll
    for (int k = 0; k < 4; k++)
#pragma unroll
        for (int r = 0; r < 8; r++) sacc[k][r] = 0.f;

    const int cbeg = (blockIdx.x * C_DIM) / NBLK;
    const int cend = ((blockIdx.x + 1) * C_DIM) / NBLK;

    for (int c = cbeg; c < cend; c++) {
        const ulonglong2* Wp = (const ulonglong2*)(W + (size_t)c * (UD * I_DIM));
        const float* xc = g_xt + c * (B_DIM * I_DIM) + wb * 64;  // 8 batches x 8 i

#pragma unroll
        for (int k = 0; k < 4; k++) {
            const int ud = wu * 128 + k * 32 + lane;
            ulonglong2 wA = Wp[2 * ud];          // W[c][ud][0..3]
            ulonglong2 wB = Wp[2 * ud + 1];      // W[c][ud][4..7]
            float cij = UNI ? (1.0f / 32.0f)
                            : __ldg(g_cij + c * U_DIM + (ud >> 4));
#pragma unroll
            for (int r = 0; r < 8; r++) {
                u64 x0, x1, x2, x3;
                ldg_2u64(xc + r * 8, x0, x1);        // warp-uniform, L1-hot
                ldg_2u64(xc + r * 8 + 4, x2, x3);
                u64 acc = mul2(wA.x, x0);
                acc = fma2(wA.y, x1, acc);
                acc = fma2(wB.x, x2, acc);
                acc = fma2(wB.y, x3, acc);
                sacc[k][r] = fmaf(cij, hadd2(acc), sacc[k][r]);
            }
        }
    }

    float* sp = g_spart + (size_t)blockIdx.x * (B_DIM * UD) + wu * 128 + lane;
#pragma unroll
    for (int r = 0; r < 8; r++)
#pragma unroll
        for (int k = 0; k < 4; k++)
            sp[(wb * 8 + r) * UD + k * 32] = sacc[k][r];
}

// ---------------------------------------------------------------------------
// k_delta: one c per block (2048 blocks, 512 threads = 16 warps).
// delta[c,u] = mean_b sum_d u_hat[b,c,u,d] * v[b,u,d]; b += delta; cij = softmax_u(b).
// Warp = (bgrp = w>>1 : 8 batches, kgrp = w&1 : ud half). Lane owns
// ud = kgrp*256 + k*32 + lane, k = 0..7.
// ---------------------------------------------------------------------------
template <int ADDB>
__global__ void __launch_bounds__(512, 2) k_delta(const float* __restrict__ W) {
    __shared__ float red_sm[8][33];

    const int c    = blockIdx.x;
    const int tid  = threadIdx.x;
    const int w    = tid >> 5;
    const int lane = tid & 31;
    const int kgrp = w & 1;
    const int bgrp = w >> 1;
    const int hw   = lane >> 4;

    // Preload this lane's 8 W rows (held across the batch loop)
    const ulonglong2* Wp = (const ulonglong2*)(W + (size_t)c * (UD * I_DIM));
    ulonglong2 wA[8], wB[8];
#pragma unroll
    for (int k = 0; k < 8; k++) {
        int ud = kgrp * 256 + k * 32 + lane;
        wA[k] = Wp[2 * ud];
        wB[k] = Wp[2 * ud + 1];
    }

    float dp[8];
#pragma unroll
    for (int k = 0; k < 8; k++) dp[k] = 0.f;

    const float* xc = g_xt + c * (B_DIM * I_DIM);

#pragma unroll
    for (int r = 0; r < 8; r++) {
        const int b = bgrp * 8 + r;
        u64 x0, x1, x2, x3;
        ldg_2u64(xc + b * 8, x0, x1);
        ldg_2u64(xc + b * 8 + 4, x2, x3);
        const float* vb = g_v + b * UD + kgrp * 256 + lane;
#pragma unroll
        for (int k = 0; k < 8; k++) {
            u64 acc = mul2(wA[k].x, x0);
            acc = fma2(wA[k].y, x1, acc);
            acc = fma2(wB[k].x, x2, acc);
            acc = fma2(wB[k].y, x3, acc);
            float vv = ldg_f(vb + k * 32);
            dp[k] = fmaf(hadd2(acc), vv, dp[k]);
        }
    }

    // reduce over d (16-lane segments); lanes 0 / 16 hold u = 2k / 2k+1
#pragma unroll
    for (int k = 0; k < 8; k++) {
        float dd = dp[k];
#pragma unroll
        for (int off = 8; off; off >>= 1)
            dd += __shfl_down_sync(0xffffffffu, dd, off, 16);
        if ((lane & 15) == 0)
            red_sm[bgrp][kgrp * 16 + 2 * k + hw] = dd;   // disjoint per warp
    }
    __syncthreads();

    if (tid < U_DIM) {
        const int u = tid;
        float delta = 0.f;
#pragma unroll
        for (int bg = 0; bg < 8; bg++) delta += red_sm[bg][u];
        float bv = delta * (1.0f / 64.0f);
        if (ADDB) bv += g_b[c * U_DIM + u];
        g_b[c * U_DIM + u] = bv;
        float m = bv;
#pragma unroll
        for (int off = 16; off; off >>= 1)
            m = fmaxf(m, __shfl_xor_sync(0xffffffffu, m, off));
        float e = __expf(bv - m);
        float s = e;
#pragma unroll
        for (int off = 16; off; off >>= 1)
            s += __shfl_xor_sync(0xffffffffu, s, off);
        g_cij[c * U_DIM + u] = e / s;
    }
}

// Reduce per-block s partials, apply squash (mag over U axis — reference quirk).
__global__ void k_redsquash(float* __restrict__ dout, int final_out) {
    __shared__ float sq_sm[UD];
    __shared__ float r_sm[D_DIM];
    int b = blockIdx.x;
    int ud = threadIdx.x;      // 512 threads
    float val = 0.f;
    const float* sp = g_spart + b * UD + ud;
#pragma unroll 4
    for (int p = 0; p < NBLK; p++) val += sp[(size_t)p * (B_DIM * UD)];
    sq_sm[ud] = val * val;
    __syncthreads();
    if (ud < D_DIM) {
        float msq = 0.f;
#pragma unroll
        for (int u = 0; u < U_DIM; u++) msq += sq_sm[u * D_DIM + ud];
        r_sm[ud] = sqrtf(msq) / (1.0f + msq);   // mag_sq/((1+mag_sq)*mag)
    }
    __syncthreads();
    float v = val * r_sm[ud & 15];
    float* dst = final_out ? dout : g_v;
    dst[b * UD + ud] = v;
}

extern "C" void kernel_launch(void* const* d_in, const int* in_sizes, int n_in,
                              void* d_out, int out_size) {
    const float* x = (const float*)d_in[0];
    const float* W = (const float*)d_in[1];
    if (n_in >= 2 && in_sizes[0] == C_DIM * U_DIM * D_DIM * I_DIM) {
        const float* t = x; x = W; W = t;
    }
    float* out = (float*)d_out;

    k_transpose<<<(C_DIM * B_DIM * I_DIM + 255) / 256, 256>>>(x);

    // iteration 1: uniform cij -> s1 -> v1
    k_accum<1><<<NBLK, 1024>>>(W);
    k_redsquash<<<B_DIM, UD>>>(out, 0);

    // iteration 2: delta(v1), b = delta, cij = softmax -> s2 -> v2
    k_delta<0><<<C_DIM, 512>>>(W);
    k_accum<0><<<NBLK, 1024>>>(W);
    k_redsquash<<<B_DIM, UD>>>(out, 0);

    // iteration 3: delta(v2), b += delta, cij = softmax -> s3 -> v3 (output)
    k_delta<1><<<C_DIM, 512>>>(W);
    k_accum<0><<<NBLK, 1024>>>(W);
    k_redsquash<<<B_DIM, UD>>>(out, 1);
}

// round 4
// speedup vs baseline: 1.0011x; 1.0011x over previous
#include <cuda_runtime.h>

#define C_DIM 2048
#define B_DIM 64
#define I_DIM 8
#define U_DIM 32
#define D_DIM 16
#define UD    512
#define NBLK  148     // k_accum grid

typedef unsigned long long u64;

// ---- scratch (static __device__: allocation-free) ----
__device__ float g_xt[C_DIM * B_DIM * I_DIM];     // x transposed: [c][b][i]
__device__ float g_spart[NBLK * B_DIM * UD];      // per-block s partials
__device__ float g_v[B_DIM * UD];                 // squashed v
__device__ float g_b[C_DIM * U_DIM];              // routing logits
__device__ float g_cij[C_DIM * U_DIM];            // softmax coupling coeffs

__device__ __forceinline__ u64 mul2(u64 a, u64 b) {
    u64 r; asm("mul.rn.f32x2 %0, %1, %2;" : "=l"(r) : "l"(a), "l"(b)); return r;
}
__device__ __forceinline__ u64 fma2(u64 a, u64 b, u64 c) {
    u64 r; asm("fma.rn.f32x2 %0, %1, %2, %3;" : "=l"(r) : "l"(a), "l"(b), "l"(c)); return r;
}
__device__ __forceinline__ float hadd2(u64 a) {
    float lo, hi; asm("mov.b64 {%0,%1}, %2;" : "=f"(lo), "=f"(hi) : "l"(a));
    return lo + hi;
}
// volatile loads: pin in place; stop ptxas hoisting loop-invariant loads into
// 32 live registers (spill bomb at 64-reg budget)
__device__ __forceinline__ float ldg_f(const float* p) {
    float r; asm volatile("ld.global.nc.f32 %0, [%1];" : "=f"(r) : "l"(p)); return r;
}
__device__ __forceinline__ void ldg_2u64(const float* p, u64& a, u64& b) {
    asm volatile("ld.global.nc.v2.u64 {%0,%1}, [%2];" : "=l"(a), "=l"(b) : "l"(p));
}

// x (B,I,C) -> g_xt[c][b][i]
__global__ void k_transpose(const float* __restrict__ x) {
    int idx = blockIdx.x * blockDim.x + threadIdx.x;
    if (idx >= C_DIM * B_DIM * I_DIM) return;
    int c = idx >> 9;
    int r = idx & 511;
    int b = r >> 3;
    int i = r & 7;
    g_xt[idx] = x[(b * I_DIM + i) * C_DIM + c];
}

// ---------------------------------------------------------------------------
// k_accum: s[b,ud] += cij[c,u] * u_hat[b,c,ud], barrier-free, s in registers.
// 1024 threads = 32 warps: wu = w&3 (ud column of 128), wb = w>>2 (8 batches).
// Lane owns ud = wu*128 + k*32 + lane, k = 0..3; batches b = wb*8 + r, r = 0..7.
// UNI=1: cij = 1/32 (first iteration).
// ---------------------------------------------------------------------------
template <int UNI>
__global__ void __launch_bounds__(1024, 1) k_accum(const float* __restrict__ W) {
    const int tid  = threadIdx.x;
    const int w    = tid >> 5;
    const int lane = tid & 31;
    const int wu   = w & 3;
    const int wb   = w >> 2;

    float sacc[4][8];
#pragma unroll
    for (int k = 0; k < 4; k++)
#pragma unroll
        for (int r = 0; r < 8; r++) sacc[k][r] = 0.f;

    const int cbeg = (blockIdx.x * C_DIM) / NBLK;
    const int cend = ((blockIdx.x + 1) * C_DIM) / NBLK;

    for (int c = cbeg; c < cend; c++) {
        const ulonglong2* Wp = (const ulonglong2*)(W + (size_t)c * (UD * I_DIM));
        const float* xc = g_xt + c * (B_DIM * I_DIM) + wb * 64;  // 8 batches x 8 i

#pragma unroll
        for (int k = 0; k < 4; k++) {
            const int ud = wu * 128 + k * 32 + lane;
            ulonglong2 wA = Wp[2 * ud];          // W[c][ud][0..3]
            ulonglong2 wB = Wp[2 * ud + 1];      // W[c][ud][4..7]
            float cij = UNI ? (1.0f / 32.0f)
                            : __ldg(g_cij + c * U_DIM + (ud >> 4));
#pragma unroll
            for (int r = 0; r < 8; r++) {
                u64 x0, x1, x2, x3;
                ldg_2u64(xc + r * 8, x0, x1);        // warp-uniform, L1-hot
                ldg_2u64(xc + r * 8 + 4, x2, x3);
                u64 acc = mul2(wA.x, x0);
                acc = fma2(wA.y, x1, acc);
                acc = fma2(wB.x, x2, acc);
                acc = fma2(wB.y, x3, acc);
                sacc[k][r] = fmaf(cij, hadd2(acc), sacc[k][r]);
            }
        }
    }

    float* sp = g_spart + (size_t)blockIdx.x * (B_DIM * UD) + wu * 128 + lane;
#pragma unroll
    for (int r = 0; r < 8; r++)
#pragma unroll
        for (int k = 0; k < 4; k++)
            sp[(wb * 8 + r) * UD + k * 32] = sacc[k][r];
}

// ---------------------------------------------------------------------------
// k_delta: one c per block (2048 blocks, 512 threads = 16 warps).
// delta[c,u] = mean_b sum_d u_hat[b,c,u,d] * v[b,u,d]; b += delta; cij = softmax_u(b).
// Warp = (bgrp = w>>1 : 8 batches, kgrp = w&1 : ud half). Lane owns
// ud = kgrp*256 + k*32 + lane, k = 0..7.
// ---------------------------------------------------------------------------
template <int ADDB>
__global__ void __launch_bounds__(512, 2) k_delta(const float* __restrict__ W) {
    __shared__ float red_sm[8][33];

    const int c    = blockIdx.x;
    const int tid  = threadIdx.x;
    const int w    = tid >> 5;
    const int lane = tid & 31;
    const int kgrp = w & 1;
    const int bgrp = w >> 1;
    const int hw   = lane >> 4;

    // Preload this lane's 8 W rows (held across the batch loop)
    const ulonglong2* Wp = (const ulonglong2*)(W + (size_t)c * (UD * I_DIM));
    ulonglong2 wA[8], wB[8];
#pragma unroll
    for (int k = 0; k < 8; k++) {
        int ud = kgrp * 256 + k * 32 + lane;
        wA[k] = Wp[2 * ud];
        wB[k] = Wp[2 * ud + 1];
    }

    float dp[8];
#pragma unroll
    for (int k = 0; k < 8; k++) dp[k] = 0.f;

    const float* xc = g_xt + c * (B_DIM * I_DIM);

#pragma unroll
    for (int r = 0; r < 8; r++) {
        const int b = bgrp * 8 + r;
        u64 x0, x1, x2, x3;
        ldg_2u64(xc + b * 8, x0, x1);
        ldg_2u64(xc + b * 8 + 4, x2, x3);
        const float* vb = g_v + b * UD + kgrp * 256 + lane;
#pragma unroll
        for (int k = 0; k < 8; k++) {
            u64 acc = mul2(wA[k].x, x0);
            acc = fma2(wA[k].y, x1, acc);
            acc = fma2(wB[k].x, x2, acc);
            acc = fma2(wB[k].y, x3, acc);
            float vv = ldg_f(vb + k * 32);
            dp[k] = fmaf(hadd2(acc), vv, dp[k]);
        }
    }

    // reduce over d (16-lane segments); lanes 0 / 16 hold u = 2k / 2k+1
#pragma unroll
    for (int k = 0; k < 8; k++) {
        float dd = dp[k];
#pragma unroll
        for (int off = 8; off; off >>= 1)
            dd += __shfl_down_sync(0xffffffffu, dd, off, 16);
        if ((lane & 15) == 0)
            red_sm[bgrp][kgrp * 16 + 2 * k + hw] = dd;   // disjoint per warp
    }
    __syncthreads();

    if (tid < U_DIM) {
        const int u = tid;
        float delta = 0.f;
#pragma unroll
        for (int bg = 0; bg < 8; bg++) delta += red_sm[bg][u];
        float bv = delta * (1.0f / 64.0f);
        if (ADDB) bv += g_b[c * U_DIM + u];
        g_b[c * U_DIM + u] = bv;
        float m = bv;
#pragma unroll
        for (int off = 16; off; off >>= 1)
            m = fmaxf(m, __shfl_xor_sync(0xffffffffu, m, off));
        float e = __expf(bv - m);
        float s = e;
#pragma unroll
        for (int off = 16; off; off >>= 1)
            s += __shfl_xor_sync(0xffffffffu, s, off);
        g_cij[c * U_DIM + u] = e / s;
    }
}

// Reduce per-block s partials, apply squash (mag over U axis — reference quirk).
__global__ void k_redsquash(float* __restrict__ dout, int final_out) {
    __shared__ float sq_sm[UD];
    __shared__ float r_sm[D_DIM];
    int b = blockIdx.x;
    int ud = threadIdx.x;      // 512 threads
    float val = 0.f;
    const float* sp = g_spart + b * UD + ud;
#pragma unroll 4
    for (int p = 0; p < NBLK; p++) val += sp[(size_t)p * (B_DIM * UD)];
    sq_sm[ud] = val * val;
    __syncthreads();
    if (ud < D_DIM) {
        float msq = 0.f;
#pragma unroll
        for (int u = 0; u < U_DIM; u++) msq += sq_sm[u * D_DIM + ud];
        r_sm[ud] = sqrtf(msq) / (1.0f + msq);   // mag_sq/((1+mag_sq)*mag)
    }
    __syncthreads();
    float v = val * r_sm[ud & 15];
    float* dst = final_out ? dout : g_v;
    dst[b * UD + ud] = v;
}

extern "C" void kernel_launch(void* const* d_in, const int* in_sizes, int n_in,
                              void* d_out, int out_size) {
    const float* x = (const float*)d_in[0];
    const float* W = (const float*)d_in[1];
    if (n_in >= 2 && in_sizes[0] == C_DIM * U_DIM * D_DIM * I_DIM) {
        const float* t = x; x = W; W = t;
    }
    float* out = (float*)d_out;

    k_transpose<<<(C_DIM * B_DIM * I_DIM + 255) / 256, 256>>>(x);

    // iteration 1: uniform cij -> s1 -> v1
    k_accum<1><<<NBLK, 1024>>>(W);
    k_redsquash<<<B_DIM, UD>>>(out, 0);

    // iteration 2: delta(v1), b = delta, cij = softmax -> s2 -> v2
    k_delta<0><<<C_DIM, 512>>>(W);
    k_accum<0><<<NBLK, 1024>>>(W);
    k_redsquash<<<B_DIM, UD>>>(out, 0);

    // iteration 3: delta(v2), b += delta, cij = softmax -> s3 -> v3 (output)
    k_delta<1><<<C_DIM, 512>>>(W);
    k_accum<0><<<NBLK, 1024>>>(W);
    k_redsquash<<<B_DIM, UD>>>(out, 1);
}

// round 5
// speedup vs baseline: 1.5306x; 1.5289x over previous
#include <cuda_runtime.h>

#define C_DIM 2048
#define B_DIM 64
#define I_DIM 8
#define U_DIM 32
#define D_DIM 16
#define UD    512
#define NBLK  148
#define NTH   512

typedef unsigned long long u64;

// ---- scratch (static __device__: allocation-free) ----
__device__ float g_xt[C_DIM * B_DIM * I_DIM];     // x transposed: [c][b][i]
__device__ float g_spart[NBLK * B_DIM * UD];      // per-block s partials
__device__ float g_v[B_DIM * UD];                 // squashed v
__device__ float g_b[C_DIM * U_DIM];              // routing logits

__device__ __forceinline__ u64 mul2(u64 a, u64 b) {
    u64 r; asm("mul.rn.f32x2 %0, %1, %2;" : "=l"(r) : "l"(a), "l"(b)); return r;
}
__device__ __forceinline__ u64 fma2(u64 a, u64 b, u64 c) {
    u64 r; asm("fma.rn.f32x2 %0, %1, %2, %3;" : "=l"(r) : "l"(a), "l"(b), "l"(c)); return r;
}
__device__ __forceinline__ float hadd2(u64 a) {
    float lo, hi; asm("mov.b64 {%0,%1}, %2;" : "=f"(lo), "=f"(hi) : "l"(a));
    return lo + hi;
}
// volatile loads: pin in place; stop ptxas hoisting c-invariant loads (spill bomb)
__device__ __forceinline__ float ldg_f(const float* p) {
    float r; asm volatile("ld.global.nc.f32 %0, [%1];" : "=f"(r) : "l"(p)); return r;
}
__device__ __forceinline__ void ldg_2u64(const float* p, u64& a, u64& b) {
    asm volatile("ld.global.nc.v2.u64 {%0,%1}, [%2];" : "=l"(a), "=l"(b) : "l"(p));
}

__device__ __forceinline__ float dot8(ulonglong2 wa, ulonglong2 wb,
                                      u64 x0, u64 x1, u64 x2, u64 x3) {
    u64 acc = mul2(wa.x, x0);
    acc = fma2(wa.y, x1, acc);
    acc = fma2(wb.x, x2, acc);
    acc = fma2(wb.y, x3, acc);
    return hadd2(acc);
}

// x (B,I,C) -> g_xt[c][b][i]
__global__ void k_transpose(const float* __restrict__ x) {
    int idx = blockIdx.x * blockDim.x + threadIdx.x;
    if (idx >= C_DIM * B_DIM * I_DIM) return;
    int c = idx >> 9;
    int r = idx & 511;
    int b = r >> 3;
    int i = r & 7;
    g_xt[idx] = x[(b * I_DIM + i) * C_DIM + c];
}

// ---------------------------------------------------------------------------
// Fused routing pass. 16 warps = 8 ud-groups (wu) x 2 b-groups (wb).
// Lane owns ud = wu*64 + k*32 + lane (k=0,1) and batches b = wb*32 + 0..31.
//   -> u = wu*4 + k*2 + (lane>>4), d = lane&15.
// W rows (2 per lane) live in registers across all 32 batches (8x less W
// traffic than warp-per-b tiling). x loads are warp-uniform broadcasts.
// PASS==0: cij = 1/32, no stash/softmax, barrier-free.
// PASS>0 : stash u_hat (self-only smem), dot with v, ONE barrier per c,
//          softmax recomputed redundantly per warp from ping-pong red_sm.
// ---------------------------------------------------------------------------
template <int PASS>
__global__ void __launch_bounds__(NTH, 1) k_pass(const float* __restrict__ W) {
    extern __shared__ float2 stash[];          // [32][NTH] : 128 KB (PASS>0)
    __shared__ float red_sm[2][2][32];         // [c-parity][wb][u]

    const int tid  = threadIdx.x;
    const int w    = tid >> 5;
    const int lane = tid & 31;
    const int wu   = w & 7;
    const int wb   = w >> 3;
    const int hw   = lane >> 4;
    const int ud0  = wu * 64 + lane;

    float sacc[2][32];
#pragma unroll
    for (int k = 0; k < 2; k++)
#pragma unroll
        for (int r = 0; r < 32; r++) sacc[k][r] = 0.f;

    const int cbeg = (blockIdx.x * C_DIM) / NBLK;
    const int cend = ((blockIdx.x + 1) * C_DIM) / NBLK;
    int par = 0;

    for (int c = cbeg; c < cend; c++) {
        const ulonglong2* Wp = (const ulonglong2*)(W + (size_t)c * (UD * I_DIM));
        ulonglong2 wA0 = Wp[2 * ud0],        wB0 = Wp[2 * ud0 + 1];
        ulonglong2 wA1 = Wp[2 * (ud0 + 32)], wB1 = Wp[2 * (ud0 + 32) + 1];
        if (c + 1 < cend)   // pull next c's W tile into L2 (512 thr x 32B = 16KB)
            asm volatile("prefetch.global.L2 [%0];"
                         :: "l"(W + (size_t)(c + 1) * (UD * I_DIM) + tid * 8));

        const float* xc = g_xt + c * (B_DIM * I_DIM) + wb * 256;  // 32 b x 8 i
        const float* vb = g_v + (wb * 32) * UD + ud0;
        float dp0 = 0.f, dp1 = 0.f;
        float bprev = (PASS == 2) ? g_b[c * U_DIM + lane] : 0.f;  // pre-barrier read

#pragma unroll
        for (int bc = 0; bc < 16; bc++) {      // 2 batches per chunk
            u64 x0, x1, x2, x3, y0, y1, y2, y3;
            ldg_2u64(xc + bc * 16,      x0, x1);   // b = wb*32 + 2bc   (uniform)
            ldg_2u64(xc + bc * 16 + 4,  x2, x3);
            ldg_2u64(xc + bc * 16 + 8,  y0, y1);   // b = wb*32 + 2bc+1 (uniform)
            ldg_2u64(xc + bc * 16 + 12, y2, y3);
            float u00 = dot8(wA0, wB0, x0, x1, x2, x3);   // k=0, r even
            float u01 = dot8(wA0, wB0, y0, y1, y2, y3);   // k=0, r odd
            float u10 = dot8(wA1, wB1, x0, x1, x2, x3);   // k=1, r even
            float u11 = dot8(wA1, wB1, y0, y1, y2, y3);   // k=1, r odd
            if (PASS > 0) {
                stash[(bc * 2 + 0) * NTH + tid] = make_float2(u00, u01);
                stash[(bc * 2 + 1) * NTH + tid] = make_float2(u10, u11);
                float v00 = ldg_f(vb + (bc * 2) * UD);
                float v01 = ldg_f(vb + (bc * 2 + 1) * UD);
                float v10 = ldg_f(vb + (bc * 2) * UD + 32);
                float v11 = ldg_f(vb + (bc * 2 + 1) * UD + 32);
                dp0 = fmaf(u00, v00, dp0);
                dp0 = fmaf(u01, v01, dp0);
                dp1 = fmaf(u10, v10, dp1);
                dp1 = fmaf(u11, v11, dp1);
            } else {
                sacc[0][bc * 2]     += u00;
                sacc[0][bc * 2 + 1] += u01;
                sacc[1][bc * 2]     += u10;
                sacc[1][bc * 2 + 1] += u11;
            }
        }

        if (PASS > 0) {
            // reduce dp over d (16-lane segments); lanes 0/16 hold u-sums
#pragma unroll
            for (int off = 8; off; off >>= 1) {
                dp0 += __shfl_down_sync(0xffffffffu, dp0, off, 16);
                dp1 += __shfl_down_sync(0xffffffffu, dp1, off, 16);
            }
            if ((lane & 15) == 0) {
                red_sm[par][wb][wu * 4 + hw]     = dp0;   // u = wu*4 + 0*2 + hw
                red_sm[par][wb][wu * 4 + 2 + hw] = dp1;   // u = wu*4 + 1*2 + hw
            }
            __syncthreads();                    // the ONLY barrier this c

            // redundant per-warp softmax over u (lane = u)
            float dv = red_sm[par][0][lane] + red_sm[par][1][lane];
            float bv = dv * (1.0f / 64.0f) + bprev;
            if (PASS == 1 && w == 0) g_b[c * U_DIM + lane] = bv;
            float m = bv;
#pragma unroll
            for (int off = 16; off; off >>= 1)
                m = fmaxf(m, __shfl_xor_sync(0xffffffffu, m, off));
            float e = __expf(bv - m);
            float ssum = e;
#pragma unroll
            for (int off = 16; off; off >>= 1)
                ssum += __shfl_xor_sync(0xffffffffu, ssum, off);
            float cij_lane = e / ssum;
            float cij0 = __shfl_sync(0xffffffffu, cij_lane, wu * 4 + hw);
            float cij1 = __shfl_sync(0xffffffffu, cij_lane, wu * 4 + 2 + hw);

            // phase B: accumulate s from self-stashed u_hat (no sync needed)
#pragma unroll
            for (int bc = 0; bc < 16; bc++) {
                float2 q0 = stash[(bc * 2 + 0) * NTH + tid];
                float2 q1 = stash[(bc * 2 + 1) * NTH + tid];
                sacc[0][bc * 2]     = fmaf(cij0, q0.x, sacc[0][bc * 2]);
                sacc[0][bc * 2 + 1] = fmaf(cij0, q0.y, sacc[0][bc * 2 + 1]);
                sacc[1][bc * 2]     = fmaf(cij1, q1.x, sacc[1][bc * 2]);
                sacc[1][bc * 2 + 1] = fmaf(cij1, q1.y, sacc[1][bc * 2 + 1]);
            }
            par ^= 1;
        }
    }

    const float scale = (PASS == 0) ? (1.0f / 32.0f) : 1.0f;
    float* sp = g_spart + (size_t)blockIdx.x * (B_DIM * UD);
#pragma unroll
    for (int r = 0; r < 32; r++)
#pragma unroll
        for (int k = 0; k < 2; k++)
            sp[(wb * 32 + r) * UD + ud0 + k * 32] = sacc[k][r] * scale;
}

// Reduce per-block s partials, apply squash (mag over U axis — reference quirk).
__global__ void k_redsquash(float* __restrict__ dout, int final_out) {
    __shared__ float sq_sm[UD];
    __shared__ float r_sm[D_DIM];
    int b = blockIdx.x;
    int ud = threadIdx.x;      // 512 threads
    float val = 0.f;
    const float* sp = g_spart + b * UD + ud;
#pragma unroll 4
    for (int p = 0; p < NBLK; p++) val += sp[(size_t)p * (B_DIM * UD)];
    sq_sm[ud] = val * val;
    __syncthreads();
    if (ud < D_DIM) {
        float msq = 0.f;
#pragma unroll
        for (int u = 0; u < U_DIM; u++) msq += sq_sm[u * D_DIM + ud];
        r_sm[ud] = sqrtf(msq) / (1.0f + msq);   // mag_sq/((1+mag_sq)*mag)
    }
    __syncthreads();
    float v = val * r_sm[ud & 15];
    float* dst = final_out ? dout : g_v;
    dst[b * UD + ud] = v;
}

extern "C" void kernel_launch(void* const* d_in, const int* in_sizes, int n_in,
                              void* d_out, int out_size) {
    const float* x = (const float*)d_in[0];
    const float* W = (const float*)d_in[1];
    if (n_in >= 2 && in_sizes[0] == C_DIM * U_DIM * D_DIM * I_DIM) {
        const float* t = x; x = W; W = t;
    }
    float* out = (float*)d_out;

    const int STASH = 32 * NTH * (int)sizeof(float2);   // 128 KB
    cudaFuncSetAttribute(k_pass<1>, cudaFuncAttributeMaxDynamicSharedMemorySize, STASH);
    cudaFuncSetAttribute(k_pass<2>, cudaFuncAttributeMaxDynamicSharedMemorySize, STASH);

    k_transpose<<<(C_DIM * B_DIM * I_DIM + 255) / 256, 256>>>(x);

    // iteration 1: uniform cij -> s1 -> v1
    k_pass<0><<<NBLK, NTH>>>(W);
    k_redsquash<<<B_DIM, UD>>>(out, 0);

    // iteration 2: delta(v1), b = delta, softmax -> s2 -> v2
    k_pass<1><<<NBLK, NTH, STASH>>>(W);
    k_redsquash<<<B_DIM, UD>>>(out, 0);

    // iteration 3: delta(v2), b += delta, softmax -> s3 -> v3 (output)
    k_pass<2><<<NBLK, NTH, STASH>>>(W);
    k_redsquash<<<B_DIM, UD>>>(out, 1);
}